// round 6
// baseline (speedup 1.0000x reference)
#include <cuda_runtime.h>
#include <cuda_fp16.h>
#include <cuda.h>
#include <cstdint>

// ----------------------------------------------------------------------------
// Problem constants
// ----------------------------------------------------------------------------
#define NROWS 8192   // x rows (output rows)
#define MROWS 8192   // y rows (output cols)
#define DDIM  512
#define GAMMA 0.002f

#define TM 128
#define TN 256
#define NTILES_X (MROWS / TN)            // 32
#define NTILES_Y (NROWS / TM)            // 64
#define NTILES   (NTILES_X * NTILES_Y)   // 2048
#define CHUNKS_PER_TILE 8                // K = 8 x 64

// tcgen05 is arch-specific (sm_103a); family (plain sm_103) pass needs a fallback.
#if !defined(__CUDA_ARCH__)
#  define USE_TCGEN05 1
#elif defined(__CUDA_ARCH_FEAT_SM103_ALL) || defined(__CUDA_ARCH_FEAT_SM100_ALL)
#  define USE_TCGEN05 1
#elif defined(__CUDA_ARCH_SPECIFIC__)
#  define USE_TCGEN05 1
#else
#  define USE_TCGEN05 0
#endif

// ----------------------------------------------------------------------------
// Scratch (device globals — no allocation allowed)
// ----------------------------------------------------------------------------
__device__ __half g_xh[NROWS * DDIM];
__device__ __half g_yh[MROWS * DDIM];
__device__ float  g_xsq[NROWS];
__device__ float  g_ysq[MROWS];

// ----------------------------------------------------------------------------
// Prep: fp32 -> fp16 + row |v|^2 (fp32 exact). One launch covers x then y.
// ----------------------------------------------------------------------------
__global__ void __launch_bounds__(256) prep_kernel(const float* __restrict__ x,
                                                   const float* __restrict__ y) {
    const int xblocks = NROWS / 8;
    const int which = (blockIdx.x >= xblocks) ? 1 : 0;
    const int blk   = which ? (blockIdx.x - xblocks) : blockIdx.x;
    const float* in = which ? y : x;
    __half* h  = which ? g_yh : g_xh;
    float* sq  = which ? g_ysq : g_xsq;

    const int warp = threadIdx.x >> 5;
    const int lane = threadIdx.x & 31;
    const int row  = blk * 8 + warp;
    const float* src = in + (size_t)row * DDIM;

    float s = 0.f;
    #pragma unroll
    for (int it = 0; it < 4; ++it) {
        const int col = it * 128 + lane * 4;
        const float4 v = *reinterpret_cast<const float4*>(src + col);
        s += v.x * v.x + v.y * v.y + v.z * v.z + v.w * v.w;
        __half2 p0 = __floats2half2_rn(v.x, v.y);
        __half2 p1 = __floats2half2_rn(v.z, v.w);
        uint2 hv = make_uint2(*reinterpret_cast<uint32_t*>(&p0),
                              *reinterpret_cast<uint32_t*>(&p1));
        *reinterpret_cast<uint2*>(h + (size_t)row * DDIM + col) = hv;
    }
    #pragma unroll
    for (int o = 16; o; o >>= 1) s += __shfl_xor_sync(0xffffffff, s, o);
    if (lane == 0) sq[row] = s;
}

// ----------------------------------------------------------------------------
// SMEM layout:
//   header 1024B: [0] tmem ptr, then mbarriers:
//     [8] full0 [16] full1 [24] done0 [32] done1
//     [40] tdone0 [48] tdone1 [56] efree0 [64] efree1
//   2 stages x (A 16K | B 32K) = 96K
// ----------------------------------------------------------------------------
#define A_TILE_BYTES  (TM * 128)              // 16384
#define B_TILE_BYTES  (TN * 128)              // 32768
#define STAGE_BYTES   (A_TILE_BYTES + B_TILE_BYTES)          // 49152
#define SMEM_FULL0    8
#define SMEM_FULL1    16
#define SMEM_DONE0    24
#define SMEM_DONE1    32
#define SMEM_TDONE0   40
#define SMEM_TDONE1   48
#define SMEM_EFREE0   56
#define SMEM_EFREE1   64
#define SMEM_TILES    1024
#define SMEM_TOTAL    (SMEM_TILES + 2 * STAGE_BYTES)         // 99328

#define NTHREADS 160   // warps 0-3 = epilogue consumers, warp 4 = producer

#if USE_TCGEN05
// ============================================================================
// tcgen05 + TMA persistent warp-specialized implementation (sm_103a only)
// ============================================================================
__device__ __forceinline__ uint32_t smem_u32(const void* p) {
    uint32_t a;
    asm("{ .reg .u64 t; cvta.to.shared.u64 t, %1; cvt.u32.u64 %0, t; }" : "=r"(a) : "l"(p));
    return a;
}
__device__ __forceinline__ uint32_t elect_one() {
    uint32_t pred;
    asm volatile("{\n\t.reg .pred p;\n\telect.sync _|p, 0xFFFFFFFF;\n\tselp.b32 %0, 1, 0, p;\n\t}"
                 : "=r"(pred));
    return pred;
}

#define TCGEN05_ALLOC(smem_addr, ncols) \
    asm volatile("tcgen05.alloc.cta_group::1.sync.aligned.shared::cta.b32 [%0], %1;" \
                 :: "r"((uint32_t)(smem_addr)), "r"((uint32_t)(ncols)) : "memory")
#define TCGEN05_DEALLOC(tmem, ncols) \
    asm volatile("tcgen05.dealloc.cta_group::1.sync.aligned.b32 %0, %1;" \
                 :: "r"(tmem), "r"((uint32_t)(ncols)))
#define TCGEN05_RELINQ() \
    asm volatile("tcgen05.relinquish_alloc_permit.cta_group::1.sync.aligned;")
#define TCGEN05_COMMIT(mbar) \
    asm volatile("tcgen05.commit.cta_group::1.mbarrier::arrive::one.shared::cluster.b64 [%0];" \
                 :: "r"((uint32_t)(mbar)) : "memory")
#define TCGEN05_WAIT_LD() asm volatile("tcgen05.wait::ld.sync.aligned;" ::: "memory")
#define TCGEN05_FENCE_AFTER()  asm volatile("tcgen05.fence::after_thread_sync;" ::: "memory")
#define TCGEN05_FENCE_BEFORE() asm volatile("tcgen05.fence::before_thread_sync;" ::: "memory")

#define MBARRIER_INIT(mbar, cnt) \
    asm volatile("mbarrier.init.shared.b64 [%0], %1;" \
                 :: "r"((uint32_t)(mbar)), "r"((uint32_t)(cnt)) : "memory")
#define MBARRIER_INVAL(mbar) \
    asm volatile("mbarrier.inval.shared.b64 [%0];" :: "r"((uint32_t)(mbar)) : "memory")
#define MBARRIER_EXPECT_TX(mbar, bytes) \
    asm volatile("mbarrier.arrive.expect_tx.shared.b64 _, [%0], %1;" \
                 :: "r"((uint32_t)(mbar)), "r"((uint32_t)(bytes)) : "memory")
#define MBARRIER_ARRIVE(mbar) \
    asm volatile("mbarrier.arrive.shared.b64 _, [%0];" :: "r"((uint32_t)(mbar)) : "memory")

#define MBARRIER_WAIT_PARITY(mbar, parity) do {                                         \
    uint32_t _m = (uint32_t)(mbar);                                                     \
    uint32_t _p = (uint32_t)(parity);                                                   \
    uint32_t _done;                                                                     \
    asm volatile("{\n\t.reg .pred p;\n\t"                                               \
                 "mbarrier.try_wait.parity.acquire.cta.shared::cta.b64 p, [%1], %2;\n\t"\
                 "selp.b32 %0, 1, 0, p;\n\t}"                                           \
                 : "=r"(_done) : "r"(_m), "r"(_p) : "memory");                          \
    if (!_done) {                                                                       \
        asm volatile("{\n\t.reg .pred P1;\n\t"                                          \
            "WAIT_LOOP_%=:\n\t"                                                         \
            "mbarrier.try_wait.parity.acquire.cta.shared::cta.b64 P1, [%0], %1, 0x989680;\n\t" \
            "@P1 bra.uni WAIT_DONE_%=;\n\t"                                             \
            "bra.uni WAIT_LOOP_%=;\n\t"                                                 \
            "WAIT_DONE_%=:\n\t}"                                                        \
            :: "r"(_m), "r"(_p) : "memory");                                            \
    }                                                                                   \
} while (0)

#define TCGEN05_LD_32X32B_X32(r, tmem_addr) \
    asm volatile( \
        "tcgen05.ld.sync.aligned.32x32b.x32.b32 " \
        "{%0, %1, %2, %3, %4, %5, %6, %7, " \
        " %8, %9, %10, %11, %12, %13, %14, %15, " \
        " %16, %17, %18, %19, %20, %21, %22, %23, " \
        " %24, %25, %26, %27, %28, %29, %30, %31}, [%32];" \
        : "=r"((r)[0]),  "=r"((r)[1]),  "=r"((r)[2]),  "=r"((r)[3]), \
          "=r"((r)[4]),  "=r"((r)[5]),  "=r"((r)[6]),  "=r"((r)[7]), \
          "=r"((r)[8]),  "=r"((r)[9]),  "=r"((r)[10]), "=r"((r)[11]), \
          "=r"((r)[12]), "=r"((r)[13]), "=r"((r)[14]), "=r"((r)[15]), \
          "=r"((r)[16]), "=r"((r)[17]), "=r"((r)[18]), "=r"((r)[19]), \
          "=r"((r)[20]), "=r"((r)[21]), "=r"((r)[22]), "=r"((r)[23]), \
          "=r"((r)[24]), "=r"((r)[25]), "=r"((r)[26]), "=r"((r)[27]), \
          "=r"((r)[28]), "=r"((r)[29]), "=r"((r)[30]), "=r"((r)[31]) \
        : "r"(tmem_addr))

__device__ __forceinline__ void tma_load_2d(uint32_t sdst, const CUtensorMap* tm,
                                            int c0, int c1, uint32_t mbar) {
    asm volatile(
        "cp.async.bulk.tensor.2d.shared::cta.global.tile.mbarrier::complete_tx::bytes "
        "[%0], [%1, {%2, %3}], [%4];"
        :: "r"(sdst), "l"(tm), "r"(c0), "r"(c1), "r"(mbar) : "memory");
}

__device__ __forceinline__ void mma_f16_ss(uint32_t d_tmem, uint64_t a_desc,
                                           uint64_t b_desc, uint32_t idesc,
                                           uint32_t enable) {
    asm volatile(
        "{\n\t.reg .pred p;\n\tsetp.ne.u32 p, %4, 0;\n\t"
        "tcgen05.mma.cta_group::1.kind::f16 [%0], %1, %2, %3, {%5, %5, %5, %5}, p;\n\t}"
        :: "r"(d_tmem), "l"(a_desc), "l"(b_desc), "r"(idesc), "r"(enable), "r"(0u)
        : "memory");
}

// SMEM descriptor: SW128, version=1(Blackwell), SBO=64, LBO=1 (K-major 128B rows)
static __device__ __forceinline__ uint64_t make_desc(uint32_t smem_addr) {
    constexpr uint64_t BASE =
        (uint64_t(2) << 61) | (uint64_t(1) << 46) | (uint64_t(64) << 32) | (uint64_t(1) << 16);
    return BASE | ((uint64_t)(smem_addr >> 4) & 0x3FFF);
}

// idesc for kind::f16, fp16 inputs, fp32 accum (bit4), N=256, M=128
#define MMA_IDESC ((1u << 4) | (((unsigned)TN / 8) << 17) | (((unsigned)TM / 16) << 24))

__global__ void __launch_bounds__(NTHREADS, 2)
rbf_gemm_kernel(const __grid_constant__ CUtensorMap tmA,
                const __grid_constant__ CUtensorMap tmB,
                const float* __restrict__ x, const float* __restrict__ y,
                float* __restrict__ out) {
    extern __shared__ __align__(1024) char smem[];
    const uint32_t sb  = smem_u32(smem);
    const int tid = threadIdx.x;
    const int wid = tid >> 5;
    const int lid = tid & 31;

    // Number of tiles this CTA handles (persistent, stride gridDim.x).
    const int ntiles = (NTILES - (int)blockIdx.x + (int)gridDim.x - 1) / (int)gridDim.x;

    if (wid == 0) {
        TCGEN05_ALLOC(sb, 512);
        TCGEN05_RELINQ();
    }
    __syncthreads();
    uint32_t tmem;
    asm volatile("ld.shared.b32 %0, [%1];" : "=r"(tmem) : "r"(sb));

    if (tid == 0) {
        MBARRIER_INIT(sb + SMEM_FULL0, 1);
        MBARRIER_INIT(sb + SMEM_FULL1, 1);
        MBARRIER_INIT(sb + SMEM_DONE0, 1);
        MBARRIER_INIT(sb + SMEM_DONE1, 1);
        MBARRIER_INIT(sb + SMEM_TDONE0, 1);
        MBARRIER_INIT(sb + SMEM_TDONE1, 1);
        MBARRIER_INIT(sb + SMEM_EFREE0, 4);   // 4 consumer warps arrive
        MBARRIER_INIT(sb + SMEM_EFREE1, 4);
    }
    __syncthreads();

    if (wid == 4) {
        // ==================== PRODUCER (single elected thread) ====================
        if (elect_one()) {
            const uint32_t full[2]  = {sb + SMEM_FULL0,  sb + SMEM_FULL1};
            const uint32_t done[2]  = {sb + SMEM_DONE0,  sb + SMEM_DONE1};
            const uint32_t tdone[2] = {sb + SMEM_TDONE0, sb + SMEM_TDONE1};
            const uint32_t efree[2] = {sb + SMEM_EFREE0, sb + SMEM_EFREE1};
            const uint32_t stage[2] = {sb + SMEM_TILES, sb + SMEM_TILES + STAGE_BYTES};
            const int total = ntiles * CHUNKS_PER_TILE;

            // Prologue: chunks 0 and 1 (both belong to the first tile).
            {
                const int tg0 = (int)blockIdx.x;
                const int rA = (tg0 >> 5) * TM;
                const int rB = (tg0 & 31) * TN;
                #pragma unroll
                for (int s = 0; s < 2; ++s) {
                    MBARRIER_EXPECT_TX(full[s], STAGE_BYTES);
                    tma_load_2d(stage[s], &tmA, s * 64, rA, full[s]);
                    tma_load_2d(stage[s] + A_TILE_BYTES, &tmB, s * 64, rB, full[s]);
                }
            }

            for (int gc = 0; gc < total; ++gc) {
                const int s   = gc & 1;
                const int k   = gc & (CHUNKS_PER_TILE - 1);
                const int lt  = gc >> 3;
                const int buf = lt & 1;

                // Before first MMA of a tile: its accumulator must be free.
                if (k == 0 && lt >= 2)
                    MBARRIER_WAIT_PARITY(efree[buf], ((lt - 2) >> 1) & 1);

                MBARRIER_WAIT_PARITY(full[s], (gc >> 1) & 1);

                const uint64_t dA = make_desc(stage[s]);
                const uint64_t dB = make_desc(stage[s] + A_TILE_BYTES);
                const uint32_t acc = tmem + buf * 256;
                #pragma unroll
                for (int kk = 0; kk < 4; ++kk)
                    mma_f16_ss(acc, dA + kk * 2, dB + kk * 2, MMA_IDESC,
                               (k == 0 && kk == 0) ? 0u : 1u);
                TCGEN05_COMMIT(done[s]);
                if (k == CHUNKS_PER_TILE - 1) TCGEN05_COMMIT(tdone[buf]);

                // Refill this stage for chunk gc+2 (possibly next tile).
                const int gn = gc + 2;
                if (gn < total) {
                    MBARRIER_WAIT_PARITY(done[s], (gc >> 1) & 1);
                    const int ltn = gn >> 3;
                    const int kn  = gn & (CHUNKS_PER_TILE - 1);
                    const int tg  = (int)blockIdx.x + ltn * (int)gridDim.x;
                    const int rA  = (tg >> 5) * TM;
                    const int rB  = (tg & 31) * TN;
                    MBARRIER_EXPECT_TX(full[s], STAGE_BYTES);
                    tma_load_2d(stage[s], &tmA, kn * 64, rA, full[s]);
                    tma_load_2d(stage[s] + A_TILE_BYTES, &tmB, kn * 64, rB, full[s]);
                }
            }
        }
    } else {
        // ==================== CONSUMERS (warps 0-3) ====================
        const uint32_t tdone[2] = {sb + SMEM_TDONE0, sb + SMEM_TDONE1};
        const uint32_t efree[2] = {sb + SMEM_EFREE0, sb + SMEM_EFREE1};

        for (int lt = 0; lt < ntiles; ++lt) {
            const int buf = lt & 1;
            MBARRIER_WAIT_PARITY(tdone[buf], (lt >> 1) & 1);
            TCGEN05_FENCE_AFTER();

            const int tg   = (int)blockIdx.x + lt * (int)gridDim.x;
            const int rowA = (tg >> 5) * TM;
            const int rowB = (tg & 31) * TN;
            const int m    = rowA + wid * 32 + lid;
            const float xs = g_xsq[m];
            float* orow = out + (size_t)m * MROWS + rowB;
            const uint32_t acc = tmem + buf * 256;

            #pragma unroll
            for (int nb = 0; nb < TN / 32; ++nb) {
                uint32_t r[32];
                TCGEN05_LD_32X32B_X32(r, acc + nb * 32);
                TCGEN05_WAIT_LD();
                #pragma unroll
                for (int j = 0; j < 32; j += 4) {
                    float4 o;
                    float d0 = xs + g_ysq[rowB + nb * 32 + j + 0] - 2.f * __uint_as_float(r[j + 0]);
                    float d1 = xs + g_ysq[rowB + nb * 32 + j + 1] - 2.f * __uint_as_float(r[j + 1]);
                    float d2 = xs + g_ysq[rowB + nb * 32 + j + 2] - 2.f * __uint_as_float(r[j + 2]);
                    float d3 = xs + g_ysq[rowB + nb * 32 + j + 3] - 2.f * __uint_as_float(r[j + 3]);
                    o.x = __expf(-GAMMA * fmaxf(d0, 0.f));
                    o.y = __expf(-GAMMA * fmaxf(d1, 0.f));
                    o.z = __expf(-GAMMA * fmaxf(d2, 0.f));
                    o.w = __expf(-GAMMA * fmaxf(d3, 0.f));
                    __stwt(reinterpret_cast<float4*>(orow + nb * 32 + j), o);
                }
            }
            TCGEN05_FENCE_BEFORE();
            if (elect_one()) MBARRIER_ARRIVE(efree[buf]);  // 1 arrival per warp
        }
    }

    __syncthreads();
    if (tid == 0) {
        MBARRIER_INVAL(sb + SMEM_FULL0);
        MBARRIER_INVAL(sb + SMEM_FULL1);
        MBARRIER_INVAL(sb + SMEM_DONE0);
        MBARRIER_INVAL(sb + SMEM_DONE1);
        MBARRIER_INVAL(sb + SMEM_TDONE0);
        MBARRIER_INVAL(sb + SMEM_TDONE1);
        MBARRIER_INVAL(sb + SMEM_EFREE0);
        MBARRIER_INVAL(sb + SMEM_EFREE1);
    }
    __syncthreads();
    if (wid == 0) TCGEN05_DEALLOC(tmem, 512);
}

#else  // !USE_TCGEN05
// ============================================================================
// SIMT fp32 fallback (family / non-'a' passes): persistent grid-stride tiles,
// 160 threads (first 128 active), 128x256 tile as two 128x128 halves.
// ============================================================================
__global__ void __launch_bounds__(NTHREADS, 2)
rbf_gemm_kernel(const __grid_constant__ CUtensorMap tmA,
                const __grid_constant__ CUtensorMap tmB,
                const float* __restrict__ x, const float* __restrict__ y,
                float* __restrict__ out) {
    extern __shared__ __align__(1024) char smem[];
    float* As = reinterpret_cast<float*>(smem);            // [16][128]
    float* Bs = As + 16 * 128;                             // [16][128]

    const int tid = threadIdx.x;
    const bool active = tid < 128;
    const int tx = tid & 15;
    const int ty = (tid >> 4) & 7;

    for (int tg = blockIdx.x; tg < NTILES; tg += gridDim.x) {
        const int rowA = (tg >> 5) * TM;
        for (int half = 0; half < 2; ++half) {
            const int rowB = (tg & 31) * TN + half * 128;

            float acc[16][8];
            #pragma unroll
            for (int i = 0; i < 16; ++i)
                #pragma unroll
                for (int j = 0; j < 8; ++j) acc[i][j] = 0.f;

            for (int k0 = 0; k0 < DDIM; k0 += 16) {
                if (active) {
                    #pragma unroll
                    for (int it = 0; it < 16; ++it) {
                        const int idx = it * 128 + tid;
                        const int r  = idx >> 4;
                        const int kk = idx & 15;
                        As[kk * 128 + r] = x[(size_t)(rowA + r) * DDIM + k0 + kk];
                        Bs[kk * 128 + r] = y[(size_t)(rowB + r) * DDIM + k0 + kk];
                    }
                }
                __syncthreads();
                if (active) {
                    #pragma unroll
                    for (int kk = 0; kk < 16; ++kk) {
                        float a[16], b[8];
                        #pragma unroll
                        for (int i = 0; i < 16; ++i) a[i] = As[kk * 128 + ty * 16 + i];
                        #pragma unroll
                        for (int j = 0; j < 8; ++j)  b[j] = Bs[kk * 128 + tx * 8 + j];
                        #pragma unroll
                        for (int i = 0; i < 16; ++i)
                            #pragma unroll
                            for (int j = 0; j < 8; ++j) acc[i][j] += a[i] * b[j];
                    }
                }
                __syncthreads();
            }

            if (active) {
                #pragma unroll
                for (int i = 0; i < 16; ++i) {
                    const int m = rowA + ty * 16 + i;
                    const float xs = g_xsq[m];
                    #pragma unroll
                    for (int j = 0; j < 8; ++j) {
                        const int cc = rowB + tx * 8 + j;
                        float d = xs + g_ysq[cc] - 2.f * acc[i][j];
                        out[(size_t)m * MROWS + cc] = __expf(-GAMMA * fmaxf(d, 0.f));
                    }
                }
            }
            __syncthreads();
        }
    }
}
#endif // USE_TCGEN05

// ----------------------------------------------------------------------------
// Host: tensor-map construction via runtime driver-entry-point (no -lcuda).
// ----------------------------------------------------------------------------
typedef CUresult (*PFN_tmapEncode)(
    CUtensorMap*, CUtensorMapDataType, cuuint32_t, void*,
    const cuuint64_t*, const cuuint64_t*, const cuuint32_t*, const cuuint32_t*,
    CUtensorMapInterleave, CUtensorMapSwizzle, CUtensorMapL2promotion,
    CUtensorMapFloatOOBfill);

static PFN_tmapEncode get_tmap_encoder() {
    void* fn = nullptr;
    cudaDriverEntryPointQueryResult st;
#if CUDART_VERSION >= 12050
    cudaGetDriverEntryPointByVersion("cuTensorMapEncodeTiled", &fn, 12000,
                                     cudaEnableDefault, &st);
#else
    cudaGetDriverEntryPoint("cuTensorMapEncodeTiled", &fn, cudaEnableDefault, &st);
#endif
    return (PFN_tmapEncode)fn;
}

static void encode_map(PFN_tmapEncode enc, CUtensorMap* tm, void* base,
                       uint64_t rows, uint32_t box_rows) {
    cuuint64_t gdim[2] = {DDIM, rows};
    cuuint64_t gstr[1] = {DDIM * sizeof(__half)};
    cuuint32_t box[2]  = {64, box_rows};          // 64 fp16 = 128B (SW128 max)
    cuuint32_t estr[2] = {1, 1};
    enc(tm, CU_TENSOR_MAP_DATA_TYPE_FLOAT16, 2, base, gdim, gstr, box, estr,
        CU_TENSOR_MAP_INTERLEAVE_NONE, CU_TENSOR_MAP_SWIZZLE_128B,
        CU_TENSOR_MAP_L2_PROMOTION_L2_128B, CU_TENSOR_MAP_FLOAT_OOB_FILL_NONE);
}

extern "C" void kernel_launch(void* const* d_in, const int* in_sizes, int n_in,
                              void* d_out, int out_size) {
    const float* x = (const float*)d_in[0];
    const float* y = (const float*)d_in[1];
    float* out = (float*)d_out;

    prep_kernel<<<NROWS / 8 + MROWS / 8, 256>>>(x, y);

    void* xh_ptr = nullptr;
    void* yh_ptr = nullptr;
    cudaGetSymbolAddress(&xh_ptr, g_xh);
    cudaGetSymbolAddress(&yh_ptr, g_yh);

    CUtensorMap tmA, tmB;
    PFN_tmapEncode enc = get_tmap_encoder();
    encode_map(enc, &tmA, xh_ptr, NROWS, TM);     // box [64, 128]
    encode_map(enc, &tmB, yh_ptr, MROWS, TN);     // box [64, 256]

    int smCount = 148;
    cudaDeviceGetAttribute(&smCount, cudaDevAttrMultiProcessorCount, 0);
    const int grid = 2 * smCount;                 // persistent, 2 CTAs/SM

    cudaFuncSetAttribute(rbf_gemm_kernel, cudaFuncAttributeMaxDynamicSharedMemorySize,
                         SMEM_TOTAL);
    rbf_gemm_kernel<<<grid, NTHREADS, SMEM_TOTAL>>>(tmA, tmB, x, y, out);
}

// round 8
// speedup vs baseline: 1.3595x; 1.3595x over previous
#include <cuda_runtime.h>
#include <cuda_fp16.h>
#include <cuda.h>
#include <cstdint>

// ----------------------------------------------------------------------------
// Problem constants
// ----------------------------------------------------------------------------
#define NROWS 8192   // x rows (output rows)
#define MROWS 8192   // y rows (output cols)
#define DDIM  512
#define GAMMA 0.002f

#define TM 128
#define TN 256

// tcgen05 is arch-specific (sm_103a); the family (plain sm_103) pass needs a fallback.
#if !defined(__CUDA_ARCH__)
#  define USE_TCGEN05 1
#elif defined(__CUDA_ARCH_FEAT_SM103_ALL) || defined(__CUDA_ARCH_FEAT_SM100_ALL)
#  define USE_TCGEN05 1
#elif defined(__CUDA_ARCH_SPECIFIC__)
#  define USE_TCGEN05 1
#else
#  define USE_TCGEN05 0
#endif

// ----------------------------------------------------------------------------
// Scratch (device globals — no allocation allowed)
// ----------------------------------------------------------------------------
__device__ __half g_xh[NROWS * DDIM];
__device__ __half g_yh[MROWS * DDIM];
__device__ float  g_xsq[NROWS];
__device__ float  g_ysq[MROWS];

// ----------------------------------------------------------------------------
// Prep: fp32 -> fp16 + row |v|^2 (fp32 exact). One launch covers x then y.
// ----------------------------------------------------------------------------
__global__ void __launch_bounds__(256) prep_kernel(const float* __restrict__ x,
                                                   const float* __restrict__ y) {
    const int xblocks = NROWS / 8;
    const int which = (blockIdx.x >= xblocks) ? 1 : 0;
    const int blk   = which ? (blockIdx.x - xblocks) : blockIdx.x;
    const float* in = which ? y : x;
    __half* h  = which ? g_yh : g_xh;
    float* sq  = which ? g_ysq : g_xsq;

    const int warp = threadIdx.x >> 5;
    const int lane = threadIdx.x & 31;
    const int row  = blk * 8 + warp;
    const float* src = in + (size_t)row * DDIM;

    float s = 0.f;
    #pragma unroll
    for (int it = 0; it < 4; ++it) {
        const int col = it * 128 + lane * 4;
        const float4 v = *reinterpret_cast<const float4*>(src + col);
        s += v.x * v.x + v.y * v.y + v.z * v.z + v.w * v.w;
        __half2 p0 = __floats2half2_rn(v.x, v.y);
        __half2 p1 = __floats2half2_rn(v.z, v.w);
        uint2 hv = make_uint2(*reinterpret_cast<uint32_t*>(&p0),
                              *reinterpret_cast<uint32_t*>(&p1));
        *reinterpret_cast<uint2*>(h + (size_t)row * DDIM + col) = hv;
    }
    #pragma unroll
    for (int o = 16; o; o >>= 1) s += __shfl_xor_sync(0xffffffff, s, o);
    if (lane == 0) sq[row] = s;
}

// ----------------------------------------------------------------------------
// SMEM layout:
//   header 1024B: [0] tmem ptr, [8] full0, [16] full1, [24] done0, [32] done1,
//                 [40] free0, [48] free1
//   2 stages x (A 16K | B 32K) = 96K
// ----------------------------------------------------------------------------
#define A_TILE_BYTES  (TM * 128)              // 16384
#define B_TILE_BYTES  (TN * 128)              // 32768
#define B_HALF_BYTES  (B_TILE_BYTES / 2)      // 16384
#define STAGE_BYTES   (A_TILE_BYTES + B_TILE_BYTES)          // 49152
#define SMEM_FULL0    8
#define SMEM_FULL1    16
#define SMEM_DONE0    24
#define SMEM_DONE1    32
#define SMEM_FREE0    40
#define SMEM_FREE1    48
#define SMEM_TILES    1024
#define SMEM_TOTAL    (SMEM_TILES + 2 * STAGE_BYTES)         // 99328

#if USE_TCGEN05
// ============================================================================
// tcgen05 + TMA + cluster-2 B-multicast implementation (sm_103a passes only)
// ============================================================================
__device__ __forceinline__ uint32_t smem_u32(const void* p) {
    uint32_t a;
    asm("{ .reg .u64 t; cvta.to.shared.u64 t, %1; cvt.u32.u64 %0, t; }" : "=r"(a) : "l"(p));
    return a;
}
__device__ __forceinline__ uint32_t cluster_rank() {
    uint32_t r;
    asm("mov.u32 %0, %%cluster_ctarank;" : "=r"(r));
    return r;
}

#define TCGEN05_ALLOC(smem_addr, ncols) \
    asm volatile("tcgen05.alloc.cta_group::1.sync.aligned.shared::cta.b32 [%0], %1;" \
                 :: "r"((uint32_t)(smem_addr)), "r"((uint32_t)(ncols)) : "memory")
#define TCGEN05_DEALLOC(tmem, ncols) \
    asm volatile("tcgen05.dealloc.cta_group::1.sync.aligned.b32 %0, %1;" \
                 :: "r"(tmem), "r"((uint32_t)(ncols)))
#define TCGEN05_RELINQ() \
    asm volatile("tcgen05.relinquish_alloc_permit.cta_group::1.sync.aligned;")
#define TCGEN05_COMMIT(mbar) \
    asm volatile("tcgen05.commit.cta_group::1.mbarrier::arrive::one.shared::cluster.b64 [%0];" \
                 :: "r"((uint32_t)(mbar)) : "memory")
#define TCGEN05_WAIT_LD() asm volatile("tcgen05.wait::ld.sync.aligned;" ::: "memory")
#define TCGEN05_FENCE_AFTER()  asm volatile("tcgen05.fence::after_thread_sync;" ::: "memory")
#define TCGEN05_FENCE_BEFORE() asm volatile("tcgen05.fence::before_thread_sync;" ::: "memory")

#define MBARRIER_INIT(mbar, cnt) \
    asm volatile("mbarrier.init.shared.b64 [%0], %1;" \
                 :: "r"((uint32_t)(mbar)), "r"((uint32_t)(cnt)) : "memory")
#define MBARRIER_INVAL(mbar) \
    asm volatile("mbarrier.inval.shared.b64 [%0];" :: "r"((uint32_t)(mbar)) : "memory")
#define MBARRIER_EXPECT_TX(mbar, bytes) \
    asm volatile("mbarrier.arrive.expect_tx.shared.b64 _, [%0], %1;" \
                 :: "r"((uint32_t)(mbar)), "r"((uint32_t)(bytes)) : "memory")

// Arrive on the mbarrier at the same SMEM offset in cluster CTA target_rank.
#define MBARRIER_ARRIVE_CLUSTER(local_mbar, target_rank) \
    asm volatile( \
        "{\n\t.reg .b32 remAddr;\n\t" \
        "mapa.shared::cluster.u32 remAddr, %0, %1;\n\t" \
        "mbarrier.arrive.shared::cluster.b64 _, [remAddr];\n\t}" \
        :: "r"((uint32_t)(local_mbar)), "r"((uint32_t)(target_rank)) : "memory")

#define CLUSTER_SYNC() do { \
    asm volatile("barrier.cluster.arrive.aligned;" ::: "memory"); \
    asm volatile("barrier.cluster.wait.aligned;" ::: "memory"); \
} while (0)

#define MBARRIER_WAIT_PARITY(mbar, parity) do {                                         \
    uint32_t _m = (uint32_t)(mbar);                                                     \
    uint32_t _p = (uint32_t)(parity);                                                   \
    uint32_t _done;                                                                     \
    asm volatile("{\n\t.reg .pred p;\n\t"                                               \
                 "mbarrier.try_wait.parity.acquire.cta.shared::cta.b64 p, [%1], %2;\n\t"\
                 "selp.b32 %0, 1, 0, p;\n\t}"                                           \
                 : "=r"(_done) : "r"(_m), "r"(_p) : "memory");                          \
    if (!_done) {                                                                       \
        asm volatile("{\n\t.reg .pred P1;\n\t"                                          \
            "WAIT_LOOP_%=:\n\t"                                                         \
            "mbarrier.try_wait.parity.acquire.cta.shared::cta.b64 P1, [%0], %1, 0x989680;\n\t" \
            "@P1 bra.uni WAIT_DONE_%=;\n\t"                                             \
            "bra.uni WAIT_LOOP_%=;\n\t"                                                 \
            "WAIT_DONE_%=:\n\t}"                                                        \
            :: "r"(_m), "r"(_p) : "memory");                                            \
    }                                                                                   \
} while (0)

#define TCGEN05_LD_32X32B_X32(r, tmem_addr) \
    asm volatile( \
        "tcgen05.ld.sync.aligned.32x32b.x32.b32 " \
        "{%0, %1, %2, %3, %4, %5, %6, %7, " \
        " %8, %9, %10, %11, %12, %13, %14, %15, " \
        " %16, %17, %18, %19, %20, %21, %22, %23, " \
        " %24, %25, %26, %27, %28, %29, %30, %31}, [%32];" \
        : "=r"((r)[0]),  "=r"((r)[1]),  "=r"((r)[2]),  "=r"((r)[3]), \
          "=r"((r)[4]),  "=r"((r)[5]),  "=r"((r)[6]),  "=r"((r)[7]), \
          "=r"((r)[8]),  "=r"((r)[9]),  "=r"((r)[10]), "=r"((r)[11]), \
          "=r"((r)[12]), "=r"((r)[13]), "=r"((r)[14]), "=r"((r)[15]), \
          "=r"((r)[16]), "=r"((r)[17]), "=r"((r)[18]), "=r"((r)[19]), \
          "=r"((r)[20]), "=r"((r)[21]), "=r"((r)[22]), "=r"((r)[23]), \
          "=r"((r)[24]), "=r"((r)[25]), "=r"((r)[26]), "=r"((r)[27]), \
          "=r"((r)[28]), "=r"((r)[29]), "=r"((r)[30]), "=r"((r)[31]) \
        : "r"(tmem_addr))

__device__ __forceinline__ void tma_load_2d(uint32_t sdst, const CUtensorMap* tm,
                                            int c0, int c1, uint32_t mbar) {
    asm volatile(
        "cp.async.bulk.tensor.2d.shared::cta.global.tile.mbarrier::complete_tx::bytes "
        "[%0], [%1, {%2, %3}], [%4];"
        :: "r"(sdst), "l"(tm), "r"(c0), "r"(c1), "r"(mbar) : "memory");
}

__device__ __forceinline__ void tma_load_2d_mc(uint32_t sdst, const CUtensorMap* tm,
                                               int c0, int c1, uint32_t mbar,
                                               uint16_t mask) {
    asm volatile(
        "cp.async.bulk.tensor.2d.shared::cluster.global.tile"
        ".mbarrier::complete_tx::bytes.multicast::cluster "
        "[%0], [%1, {%2, %3}], [%4], %5;"
        :: "r"(sdst), "l"(tm), "r"(c0), "r"(c1), "r"(mbar), "h"(mask) : "memory");
}

__device__ __forceinline__ void mma_f16_ss(uint32_t d_tmem, uint64_t a_desc,
                                           uint64_t b_desc, uint32_t idesc,
                                           uint32_t enable) {
    asm volatile(
        "{\n\t.reg .pred p;\n\tsetp.ne.u32 p, %4, 0;\n\t"
        "tcgen05.mma.cta_group::1.kind::f16 [%0], %1, %2, %3, {%5, %5, %5, %5}, p;\n\t}"
        :: "r"(d_tmem), "l"(a_desc), "l"(b_desc), "r"(idesc), "r"(enable), "r"(0u)
        : "memory");
}

// SMEM descriptor: SW128, version=1(Blackwell), SBO=64, LBO=1 (K-major 128B rows)
static __device__ __forceinline__ uint64_t make_desc(uint32_t smem_addr) {
    constexpr uint64_t BASE =
        (uint64_t(2) << 61) | (uint64_t(1) << 46) | (uint64_t(64) << 32) | (uint64_t(1) << 16);
    return BASE | ((uint64_t)(smem_addr >> 4) & 0x3FFF);
}

// idesc for kind::f16, fp16 inputs, fp32 accum (bit4), N=256, M=128
#define MMA_IDESC ((1u << 4) | (((unsigned)TN / 8) << 17) | (((unsigned)TM / 16) << 24))

__global__ void __launch_bounds__(128, 2) __cluster_dims__(1, 2, 1)
rbf_gemm_kernel(const __grid_constant__ CUtensorMap tmA,
                const __grid_constant__ CUtensorMap tmB,
                const float* __restrict__ x, const float* __restrict__ y,
                float* __restrict__ out) {
    extern __shared__ __align__(1024) char smem[];
    const uint32_t sb  = smem_u32(smem);
    const int tid = threadIdx.x;
    const int wid = tid >> 5;
    const int lid = tid & 31;
    const uint32_t rank = cluster_rank();      // 0 or 1 within the y-pair

    if (wid == 0) {
        TCGEN05_ALLOC(sb, 256);
        TCGEN05_RELINQ();
    }
    __syncthreads();
    uint32_t tmem;
    asm volatile("ld.shared.b32 %0, [%1];" : "=r"(tmem) : "r"(sb));

    if (tid == 0) {
        MBARRIER_INIT(sb + SMEM_FULL0, 1);
        MBARRIER_INIT(sb + SMEM_FULL1, 1);
        MBARRIER_INIT(sb + SMEM_DONE0, 1);
        MBARRIER_INIT(sb + SMEM_DONE1, 1);
        MBARRIER_INIT(sb + SMEM_FREE0, 1);   // peer's "my MMA done" arrive
        MBARRIER_INIT(sb + SMEM_FREE1, 1);
    }
    __syncthreads();
    // All mbarriers in both CTAs must be live before any multicast TMA.
    CLUSTER_SYNC();

    const int rowA = blockIdx.y * TM;          // cluster pair: rowA, rowA+TM
    const int rowB = blockIdx.x * TN;          // shared across the pair

    // ------------------------------------------------------------------
    // Mainloop: single thread. Per stage: A per-CTA TMA + B-half multicast
    // (each CTA loads a distinct 128-row half of B, delivered to both).
    // Refill of a stage waits for BOTH CTAs' MMAs on it (done + peer free).
    // ------------------------------------------------------------------
    if (tid == 0) {
        const uint32_t full[2] = {sb + SMEM_FULL0, sb + SMEM_FULL1};
        const uint32_t done[2] = {sb + SMEM_DONE0, sb + SMEM_DONE1};
        const uint32_t freeb[2] = {sb + SMEM_FREE0, sb + SMEM_FREE1};
        const uint32_t stage[2] = {sb + SMEM_TILES, sb + SMEM_TILES + STAGE_BYTES};
        const int bHalfRow = rowB + (int)rank * (TN / 2);
        const uint32_t bHalfOff = A_TILE_BYTES + rank * B_HALF_BYTES;

        // Prologue: chunks 0,1 into stages 0,1.
        #pragma unroll
        for (int s = 0; s < 2; ++s) {
            MBARRIER_EXPECT_TX(full[s], STAGE_BYTES);
            tma_load_2d(stage[s], &tmA, s * 64, rowA, full[s]);
            tma_load_2d_mc(stage[s] + bHalfOff, &tmB, s * 64, bHalfRow, full[s], 0x3);
        }

        int fr[2] = {0, 0};   // free-barrier wait parities

        #pragma unroll
        for (int c = 0; c < 8; ++c) {
            const int s = c & 1;
            MBARRIER_WAIT_PARITY(full[s], (c >> 1) & 1);

            const uint64_t dA = make_desc(stage[s]);
            const uint64_t dB = make_desc(stage[s] + A_TILE_BYTES);
            #pragma unroll
            for (int k = 0; k < 4; ++k)
                mma_f16_ss(tmem, dA + k * 2, dB + k * 2, MMA_IDESC,
                           (c == 0 && k == 0) ? 0u : 1u);
            TCGEN05_COMMIT(done[s]);

            if (c + 2 < 8) {
                // My MMAs on stage s done:
                MBARRIER_WAIT_PARITY(done[s], (c >> 1) & 1);
                // Tell peer, then wait for peer's (arrive-before-wait: no deadlock).
                MBARRIER_ARRIVE_CLUSTER(freeb[s], rank ^ 1u);
                MBARRIER_WAIT_PARITY(freeb[s], fr[s] & 1);
                fr[s]++;
                MBARRIER_EXPECT_TX(full[s], STAGE_BYTES);
                tma_load_2d(stage[s], &tmA, (c + 2) * 64, rowA, full[s]);
                tma_load_2d_mc(stage[s] + bHalfOff, &tmB, (c + 2) * 64, bHalfRow,
                               full[s], 0x3);
            }
        }
        // Chunk 7's commit (2nd arrival on done[1] -> phase back to 1... track:
        // done[1] arrivals at c=1,3,5,7; waits consumed c=1,3,5 -> wait phase 1.
        MBARRIER_WAIT_PARITY(done[1], 1);
    }

    __syncthreads();
    TCGEN05_FENCE_AFTER();

    // ------------------------------------------------------------------
    // Epilogue: each warp owns its 32-row TMEM subpartition; TN=256 cols.
    // __stwt keeps the fp16 operand set L2-resident.
    // ------------------------------------------------------------------
    const int m = rowA + wid * 32 + lid;
    const float xs = g_xsq[m];
    float* orow = out + (size_t)m * MROWS + rowB;

    #pragma unroll
    for (int nb = 0; nb < TN / 32; ++nb) {
        uint32_t r[32];
        TCGEN05_LD_32X32B_X32(r, tmem + nb * 32);
        TCGEN05_WAIT_LD();
        #pragma unroll
        for (int j = 0; j < 32; j += 4) {
            float4 o;
            float d0 = xs + g_ysq[rowB + nb * 32 + j + 0] - 2.f * __uint_as_float(r[j + 0]);
            float d1 = xs + g_ysq[rowB + nb * 32 + j + 1] - 2.f * __uint_as_float(r[j + 1]);
            float d2 = xs + g_ysq[rowB + nb * 32 + j + 2] - 2.f * __uint_as_float(r[j + 2]);
            float d3 = xs + g_ysq[rowB + nb * 32 + j + 3] - 2.f * __uint_as_float(r[j + 3]);
            o.x = __expf(-GAMMA * fmaxf(d0, 0.f));
            o.y = __expf(-GAMMA * fmaxf(d1, 0.f));
            o.z = __expf(-GAMMA * fmaxf(d2, 0.f));
            o.w = __expf(-GAMMA * fmaxf(d3, 0.f));
            __stwt(reinterpret_cast<float4*>(orow + nb * 32 + j), o);
        }
    }
    TCGEN05_FENCE_BEFORE();

    __syncthreads();
    if (tid == 0) {
        MBARRIER_INVAL(sb + SMEM_FULL0);
        MBARRIER_INVAL(sb + SMEM_FULL1);
        MBARRIER_INVAL(sb + SMEM_DONE0);
        MBARRIER_INVAL(sb + SMEM_DONE1);
        MBARRIER_INVAL(sb + SMEM_FREE0);
        MBARRIER_INVAL(sb + SMEM_FREE1);
    }
    __syncthreads();
    if (wid == 0) TCGEN05_DEALLOC(tmem, 256);
    // No CTA may exit while the peer's multicasts / remote arrives could still
    // target this CTA's SMEM.
    CLUSTER_SYNC();
}

#else  // !USE_TCGEN05
// ============================================================================
// SIMT fp32 fallback (family / non-'a' passes): same signature/geometry,
// tile = 128 x 256 handled as two 128x128 halves. Uses x/y directly.
// ============================================================================
__global__ void __launch_bounds__(128, 2) __cluster_dims__(1, 2, 1)
rbf_gemm_kernel(const __grid_constant__ CUtensorMap tmA,
                const __grid_constant__ CUtensorMap tmB,
                const float* __restrict__ x, const float* __restrict__ y,
                float* __restrict__ out) {
    extern __shared__ __align__(1024) char smem[];
    float* As = reinterpret_cast<float*>(smem);            // [16][128]
    float* Bs = As + 16 * 128;                             // [16][128]

    const int tid = threadIdx.x;
    const int tx = tid & 15;
    const int ty = tid >> 4;
    const int rowA = blockIdx.y * TM;

    for (int half = 0; half < 2; ++half) {
        const int rowB = blockIdx.x * TN + half * 128;

        float acc[16][8];
        #pragma unroll
        for (int i = 0; i < 16; ++i)
            #pragma unroll
            for (int j = 0; j < 8; ++j) acc[i][j] = 0.f;

        for (int k0 = 0; k0 < DDIM; k0 += 16) {
            #pragma unroll
            for (int it = 0; it < 16; ++it) {
                const int idx = it * 128 + tid;
                const int r  = idx >> 4;
                const int kk = idx & 15;
                As[kk * 128 + r] = x[(size_t)(rowA + r) * DDIM + k0 + kk];
                Bs[kk * 128 + r] = y[(size_t)(rowB + r) * DDIM + k0 + kk];
            }
            __syncthreads();
            #pragma unroll
            for (int kk = 0; kk < 16; ++kk) {
                float a[16], b[8];
                #pragma unroll
                for (int i = 0; i < 16; ++i) a[i] = As[kk * 128 + ty * 16 + i];
                #pragma unroll
                for (int j = 0; j < 8; ++j)  b[j] = Bs[kk * 128 + tx * 8 + j];
                #pragma unroll
                for (int i = 0; i < 16; ++i)
                    #pragma unroll
                    for (int j = 0; j < 8; ++j) acc[i][j] += a[i] * b[j];
            }
            __syncthreads();
        }

        #pragma unroll
        for (int i = 0; i < 16; ++i) {
            const int m = rowA + ty * 16 + i;
            const float xs = g_xsq[m];
            #pragma unroll
            for (int j = 0; j < 8; ++j) {
                const int cc = rowB + tx * 8 + j;
                float d = xs + g_ysq[cc] - 2.f * acc[i][j];
                out[(size_t)m * MROWS + cc] = __expf(-GAMMA * fmaxf(d, 0.f));
            }
        }
        __syncthreads();
    }
}
#endif // USE_TCGEN05

// ----------------------------------------------------------------------------
// Host: tensor-map construction via runtime driver-entry-point (no -lcuda).
// ----------------------------------------------------------------------------
typedef CUresult (*PFN_tmapEncode)(
    CUtensorMap*, CUtensorMapDataType, cuuint32_t, void*,
    const cuuint64_t*, const cuuint64_t*, const cuuint32_t*, const cuuint32_t*,
    CUtensorMapInterleave, CUtensorMapSwizzle, CUtensorMapL2promotion,
    CUtensorMapFloatOOBfill);

static PFN_tmapEncode get_tmap_encoder() {
    void* fn = nullptr;
    cudaDriverEntryPointQueryResult st;
#if CUDART_VERSION >= 12050
    cudaGetDriverEntryPointByVersion("cuTensorMapEncodeTiled", &fn, 12000,
                                     cudaEnableDefault, &st);
#else
    cudaGetDriverEntryPoint("cuTensorMapEncodeTiled", &fn, cudaEnableDefault, &st);
#endif
    return (PFN_tmapEncode)fn;
}

static void encode_map(PFN_tmapEncode enc, CUtensorMap* tm, void* base,
                       uint64_t rows, uint32_t box_rows) {
    cuuint64_t gdim[2] = {DDIM, rows};
    cuuint64_t gstr[1] = {DDIM * sizeof(__half)};
    cuuint32_t box[2]  = {64, box_rows};          // 64 fp16 = 128B (SW128 max)
    cuuint32_t estr[2] = {1, 1};
    enc(tm, CU_TENSOR_MAP_DATA_TYPE_FLOAT16, 2, base, gdim, gstr, box, estr,
        CU_TENSOR_MAP_INTERLEAVE_NONE, CU_TENSOR_MAP_SWIZZLE_128B,
        CU_TENSOR_MAP_L2_PROMOTION_L2_128B, CU_TENSOR_MAP_FLOAT_OOB_FILL_NONE);
}

extern "C" void kernel_launch(void* const* d_in, const int* in_sizes, int n_in,
                              void* d_out, int out_size) {
    const float* x = (const float*)d_in[0];
    const float* y = (const float*)d_in[1];
    float* out = (float*)d_out;

    prep_kernel<<<NROWS / 8 + MROWS / 8, 256>>>(x, y);

    void* xh_ptr = nullptr;
    void* yh_ptr = nullptr;
    cudaGetSymbolAddress(&xh_ptr, g_xh);
    cudaGetSymbolAddress(&yh_ptr, g_yh);

    CUtensorMap tmA, tmB;
    PFN_tmapEncode enc = get_tmap_encoder();
    encode_map(enc, &tmA, xh_ptr, NROWS, TM);       // box [64, 128]
    encode_map(enc, &tmB, yh_ptr, MROWS, TN / 2);   // box [64, 128] (B half)

    cudaFuncSetAttribute(rbf_gemm_kernel, cudaFuncAttributeMaxDynamicSharedMemorySize,
                         SMEM_TOTAL);
    dim3 grid(MROWS / TN, NROWS / TM);              // (32, 64); cluster (1,2,1)
    rbf_gemm_kernel<<<grid, 128, SMEM_TOTAL>>>(tmA, tmB, x, y, out);
}

// round 9
// speedup vs baseline: 1.3995x; 1.0295x over previous
#include <cuda_runtime.h>
#include <cuda_fp16.h>
#include <cuda.h>
#include <cstdint>

// ----------------------------------------------------------------------------
// Problem constants
// ----------------------------------------------------------------------------
#define NROWS 8192   // x rows (output rows)
#define MROWS 8192   // y rows (output cols)
#define DDIM  512
#define GAMMA 0.002f

#define TM 128
#define TN 256
#define CHUNK_K 32                   // fp16 elems per K-chunk (64B rows, SW64)
#define NCHUNKS (DDIM / CHUNK_K)     // 16
#define NSTAGES 4

// tcgen05 is arch-specific (sm_103a); the family (plain sm_103) pass needs a fallback.
#if !defined(__CUDA_ARCH__)
#  define USE_TCGEN05 1
#elif defined(__CUDA_ARCH_FEAT_SM103_ALL) || defined(__CUDA_ARCH_FEAT_SM100_ALL)
#  define USE_TCGEN05 1
#elif defined(__CUDA_ARCH_SPECIFIC__)
#  define USE_TCGEN05 1
#else
#  define USE_TCGEN05 0
#endif

// ----------------------------------------------------------------------------
// Scratch (device globals — no allocation allowed)
// ----------------------------------------------------------------------------
__device__ __half g_xh[NROWS * DDIM];
__device__ __half g_yh[MROWS * DDIM];
__device__ float  g_xsq[NROWS];
__device__ float  g_ysq[MROWS];

// ----------------------------------------------------------------------------
// Prep: fp32 -> fp16 + row |v|^2 (fp32 exact). One launch covers x then y.
// ----------------------------------------------------------------------------
__global__ void __launch_bounds__(256) prep_kernel(const float* __restrict__ x,
                                                   const float* __restrict__ y) {
    const int xblocks = NROWS / 8;
    const int which = (blockIdx.x >= xblocks) ? 1 : 0;
    const int blk   = which ? (blockIdx.x - xblocks) : blockIdx.x;
    const float* in = which ? y : x;
    __half* h  = which ? g_yh : g_xh;
    float* sq  = which ? g_ysq : g_xsq;

    const int warp = threadIdx.x >> 5;
    const int lane = threadIdx.x & 31;
    const int row  = blk * 8 + warp;
    const float* src = in + (size_t)row * DDIM;

    float s = 0.f;
    #pragma unroll
    for (int it = 0; it < 4; ++it) {
        const int col = it * 128 + lane * 4;
        const float4 v = *reinterpret_cast<const float4*>(src + col);
        s += v.x * v.x + v.y * v.y + v.z * v.z + v.w * v.w;
        __half2 p0 = __floats2half2_rn(v.x, v.y);
        __half2 p1 = __floats2half2_rn(v.z, v.w);
        uint2 hv = make_uint2(*reinterpret_cast<uint32_t*>(&p0),
                              *reinterpret_cast<uint32_t*>(&p1));
        *reinterpret_cast<uint2*>(h + (size_t)row * DDIM + col) = hv;
    }
    #pragma unroll
    for (int o = 16; o; o >>= 1) s += __shfl_xor_sync(0xffffffff, s, o);
    if (lane == 0) sq[row] = s;
}

// ----------------------------------------------------------------------------
// SMEM layout:
//   header 1024B: [0] tmem ptr, full[s] at 8+8s (s=0..3), done[s] at 40+8s
//   4 stages x (A 8K | B 16K) = 96K     -> total 99328 (2 CTAs/SM)
// ----------------------------------------------------------------------------
#define A_TILE_BYTES  (TM * CHUNK_K * 2)      // 8192  (64B rows)
#define B_TILE_BYTES  (TN * CHUNK_K * 2)      // 16384
#define STAGE_BYTES   (A_TILE_BYTES + B_TILE_BYTES)          // 24576
#define SMEM_FULL(s)  (8 + 8 * (s))
#define SMEM_DONE(s)  (40 + 8 * (s))
#define SMEM_TILES    1024
#define SMEM_TOTAL    (SMEM_TILES + NSTAGES * STAGE_BYTES)   // 99328

#if USE_TCGEN05
// ============================================================================
// tcgen05 + TMA (SW64, 4-stage) implementation (sm_103a passes only)
// ============================================================================
__device__ __forceinline__ uint32_t smem_u32(const void* p) {
    uint32_t a;
    asm("{ .reg .u64 t; cvta.to.shared.u64 t, %1; cvt.u32.u64 %0, t; }" : "=r"(a) : "l"(p));
    return a;
}

#define TCGEN05_ALLOC(smem_addr, ncols) \
    asm volatile("tcgen05.alloc.cta_group::1.sync.aligned.shared::cta.b32 [%0], %1;" \
                 :: "r"((uint32_t)(smem_addr)), "r"((uint32_t)(ncols)) : "memory")
#define TCGEN05_DEALLOC(tmem, ncols) \
    asm volatile("tcgen05.dealloc.cta_group::1.sync.aligned.b32 %0, %1;" \
                 :: "r"(tmem), "r"((uint32_t)(ncols)))
#define TCGEN05_RELINQ() \
    asm volatile("tcgen05.relinquish_alloc_permit.cta_group::1.sync.aligned;")
#define TCGEN05_COMMIT(mbar) \
    asm volatile("tcgen05.commit.cta_group::1.mbarrier::arrive::one.shared::cluster.b64 [%0];" \
                 :: "r"((uint32_t)(mbar)) : "memory")
#define TCGEN05_WAIT_LD() asm volatile("tcgen05.wait::ld.sync.aligned;" ::: "memory")
#define TCGEN05_FENCE_AFTER()  asm volatile("tcgen05.fence::after_thread_sync;" ::: "memory")
#define TCGEN05_FENCE_BEFORE() asm volatile("tcgen05.fence::before_thread_sync;" ::: "memory")

#define MBARRIER_INIT(mbar, cnt) \
    asm volatile("mbarrier.init.shared.b64 [%0], %1;" \
                 :: "r"((uint32_t)(mbar)), "r"((uint32_t)(cnt)) : "memory")
#define MBARRIER_INVAL(mbar) \
    asm volatile("mbarrier.inval.shared.b64 [%0];" :: "r"((uint32_t)(mbar)) : "memory")
#define MBARRIER_EXPECT_TX(mbar, bytes) \
    asm volatile("mbarrier.arrive.expect_tx.shared.b64 _, [%0], %1;" \
                 :: "r"((uint32_t)(mbar)), "r"((uint32_t)(bytes)) : "memory")

#define MBARRIER_WAIT_PARITY(mbar, parity) do {                                         \
    uint32_t _m = (uint32_t)(mbar);                                                     \
    uint32_t _p = (uint32_t)(parity);                                                   \
    uint32_t _done;                                                                     \
    asm volatile("{\n\t.reg .pred p;\n\t"                                               \
                 "mbarrier.try_wait.parity.acquire.cta.shared::cta.b64 p, [%1], %2;\n\t"\
                 "selp.b32 %0, 1, 0, p;\n\t}"                                           \
                 : "=r"(_done) : "r"(_m), "r"(_p) : "memory");                          \
    if (!_done) {                                                                       \
        asm volatile("{\n\t.reg .pred P1;\n\t"                                          \
            "WAIT_LOOP_%=:\n\t"                                                         \
            "mbarrier.try_wait.parity.acquire.cta.shared::cta.b64 P1, [%0], %1, 0x989680;\n\t" \
            "@P1 bra.uni WAIT_DONE_%=;\n\t"                                             \
            "bra.uni WAIT_LOOP_%=;\n\t"                                                 \
            "WAIT_DONE_%=:\n\t}"                                                        \
            :: "r"(_m), "r"(_p) : "memory");                                            \
    }                                                                                   \
} while (0)

#define TCGEN05_LD_32X32B_X32(r, tmem_addr) \
    asm volatile( \
        "tcgen05.ld.sync.aligned.32x32b.x32.b32 " \
        "{%0, %1, %2, %3, %4, %5, %6, %7, " \
        " %8, %9, %10, %11, %12, %13, %14, %15, " \
        " %16, %17, %18, %19, %20, %21, %22, %23, " \
        " %24, %25, %26, %27, %28, %29, %30, %31}, [%32];" \
        : "=r"((r)[0]),  "=r"((r)[1]),  "=r"((r)[2]),  "=r"((r)[3]), \
          "=r"((r)[4]),  "=r"((r)[5]),  "=r"((r)[6]),  "=r"((r)[7]), \
          "=r"((r)[8]),  "=r"((r)[9]),  "=r"((r)[10]), "=r"((r)[11]), \
          "=r"((r)[12]), "=r"((r)[13]), "=r"((r)[14]), "=r"((r)[15]), \
          "=r"((r)[16]), "=r"((r)[17]), "=r"((r)[18]), "=r"((r)[19]), \
          "=r"((r)[20]), "=r"((r)[21]), "=r"((r)[22]), "=r"((r)[23]), \
          "=r"((r)[24]), "=r"((r)[25]), "=r"((r)[26]), "=r"((r)[27]), \
          "=r"((r)[28]), "=r"((r)[29]), "=r"((r)[30]), "=r"((r)[31]) \
        : "r"(tmem_addr))

__device__ __forceinline__ void tma_load_2d(uint32_t sdst, const CUtensorMap* tm,
                                            int c0, int c1, uint32_t mbar) {
    asm volatile(
        "cp.async.bulk.tensor.2d.shared::cta.global.tile.mbarrier::complete_tx::bytes "
        "[%0], [%1, {%2, %3}], [%4];"
        :: "r"(sdst), "l"(tm), "r"(c0), "r"(c1), "r"(mbar) : "memory");
}

__device__ __forceinline__ void mma_f16_ss(uint32_t d_tmem, uint64_t a_desc,
                                           uint64_t b_desc, uint32_t idesc,
                                           uint32_t enable) {
    asm volatile(
        "{\n\t.reg .pred p;\n\tsetp.ne.u32 p, %4, 0;\n\t"
        "tcgen05.mma.cta_group::1.kind::f16 [%0], %1, %2, %3, {%5, %5, %5, %5}, p;\n\t}"
        :: "r"(d_tmem), "l"(a_desc), "l"(b_desc), "r"(idesc), "r"(enable), "r"(0u)
        : "memory");
}

// SW64 SMEM descriptor: layout=4, version=1(Blackwell), SBO=32 (8 rows x 64B =
// 512B), LBO=1 (16B inner). 64-byte K-major rows.
static __device__ __forceinline__ uint64_t make_desc_sw64(uint32_t smem_addr) {
    constexpr uint64_t BASE =
        (uint64_t(4) << 61) | (uint64_t(1) << 46) | (uint64_t(32) << 32) | (uint64_t(1) << 16);
    return BASE | ((uint64_t)(smem_addr >> 4) & 0x3FFF);
}

// idesc for kind::f16, fp16 inputs, fp32 accum (bit4), N=256, M=128
#define MMA_IDESC ((1u << 4) | (((unsigned)TN / 8) << 17) | (((unsigned)TM / 16) << 24))

__global__ void __launch_bounds__(128, 2)
rbf_gemm_kernel(const __grid_constant__ CUtensorMap tmA,
                const __grid_constant__ CUtensorMap tmB,
                const float* __restrict__ x, const float* __restrict__ y,
                float* __restrict__ out) {
    extern __shared__ __align__(1024) char smem[];
    const uint32_t sb  = smem_u32(smem);
    const int tid = threadIdx.x;
    const int wid = tid >> 5;
    const int lid = tid & 31;

    if (wid == 0) {
        TCGEN05_ALLOC(sb, 256);
        TCGEN05_RELINQ();
    }
    __syncthreads();
    uint32_t tmem;
    asm volatile("ld.shared.b32 %0, [%1];" : "=r"(tmem) : "r"(sb));

    if (tid == 0) {
        #pragma unroll
        for (int s = 0; s < NSTAGES; ++s) {
            MBARRIER_INIT(sb + SMEM_FULL(s), 1);
            MBARRIER_INIT(sb + SMEM_DONE(s), 1);
        }
    }
    __syncthreads();

    const int rowA = blockIdx.y * TM;
    const int rowB = blockIdx.x * TN;

    // ------------------------------------------------------------------
    // Mainloop: single thread, 4-stage pipeline of K=32 chunks. Refill of
    // stage s (chunk c+4) waits on MMA completion of chunk c — with 4
    // stages that completion happened ~3 chunks ago, so up to 3 TMA loads
    // (72KB) are in flight per CTA and round-trip latency is amortized.
    // ------------------------------------------------------------------
    if (tid == 0) {
        // Prologue: chunks 0..3 into stages 0..3.
        #pragma unroll
        for (int s = 0; s < NSTAGES; ++s) {
            const uint32_t st = sb + SMEM_TILES + s * STAGE_BYTES;
            MBARRIER_EXPECT_TX(sb + SMEM_FULL(s), STAGE_BYTES);
            tma_load_2d(st, &tmA, s * CHUNK_K, rowA, sb + SMEM_FULL(s));
            tma_load_2d(st + A_TILE_BYTES, &tmB, s * CHUNK_K, rowB, sb + SMEM_FULL(s));
        }

        #pragma unroll
        for (int c = 0; c < NCHUNKS; ++c) {
            const int s = c & (NSTAGES - 1);
            const int n = c >> 2;                 // use-count of stage s
            const uint32_t st = sb + SMEM_TILES + s * STAGE_BYTES;

            MBARRIER_WAIT_PARITY(sb + SMEM_FULL(s), n & 1);

            const uint64_t dA = make_desc_sw64(st);
            const uint64_t dB = make_desc_sw64(st + A_TILE_BYTES);
            // 2 x K=16 MMAs; +32B (=2 desc units) per step within the 64B row.
            mma_f16_ss(tmem, dA,     dB,     MMA_IDESC, (c == 0) ? 0u : 1u);
            mma_f16_ss(tmem, dA + 2, dB + 2, MMA_IDESC, 1u);
            TCGEN05_COMMIT(sb + SMEM_DONE(s));

            const int gn = c + NSTAGES;
            if (gn < NCHUNKS) {
                MBARRIER_WAIT_PARITY(sb + SMEM_DONE(s), n & 1);
                MBARRIER_EXPECT_TX(sb + SMEM_FULL(s), STAGE_BYTES);
                tma_load_2d(st, &tmA, gn * CHUNK_K, rowA, sb + SMEM_FULL(s));
                tma_load_2d(st + A_TILE_BYTES, &tmB, gn * CHUNK_K, rowB,
                            sb + SMEM_FULL(s));
            }
        }
        // Last chunk (c=15) committed on done[3]; its arrival count there is 4
        // (c=3,7,11,15), waits consumed 3 (parities 0,1,0) -> final parity 1.
        MBARRIER_WAIT_PARITY(sb + SMEM_DONE(3), 1);
    }

    __syncthreads();
    TCGEN05_FENCE_AFTER();

    // ------------------------------------------------------------------
    // Epilogue: each warp owns its 32-row TMEM subpartition; TN=256 cols.
    // __stwt keeps the fp16 operand set L2-resident.
    // ------------------------------------------------------------------
    const int m = rowA + wid * 32 + lid;
    const float xs = g_xsq[m];
    float* orow = out + (size_t)m * MROWS + rowB;

    #pragma unroll
    for (int nb = 0; nb < TN / 32; ++nb) {
        uint32_t r[32];
        TCGEN05_LD_32X32B_X32(r, tmem + nb * 32);
        TCGEN05_WAIT_LD();
        #pragma unroll
        for (int j = 0; j < 32; j += 4) {
            float4 o;
            float d0 = xs + g_ysq[rowB + nb * 32 + j + 0] - 2.f * __uint_as_float(r[j + 0]);
            float d1 = xs + g_ysq[rowB + nb * 32 + j + 1] - 2.f * __uint_as_float(r[j + 1]);
            float d2 = xs + g_ysq[rowB + nb * 32 + j + 2] - 2.f * __uint_as_float(r[j + 2]);
            float d3 = xs + g_ysq[rowB + nb * 32 + j + 3] - 2.f * __uint_as_float(r[j + 3]);
            o.x = __expf(-GAMMA * fmaxf(d0, 0.f));
            o.y = __expf(-GAMMA * fmaxf(d1, 0.f));
            o.z = __expf(-GAMMA * fmaxf(d2, 0.f));
            o.w = __expf(-GAMMA * fmaxf(d3, 0.f));
            __stwt(reinterpret_cast<float4*>(orow + nb * 32 + j), o);
        }
    }
    TCGEN05_FENCE_BEFORE();

    __syncthreads();
    if (tid == 0) {
        #pragma unroll
        for (int s = 0; s < NSTAGES; ++s) {
            MBARRIER_INVAL(sb + SMEM_FULL(s));
            MBARRIER_INVAL(sb + SMEM_DONE(s));
        }
    }
    __syncthreads();
    if (wid == 0) TCGEN05_DEALLOC(tmem, 256);
}

#else  // !USE_TCGEN05
// ============================================================================
// SIMT fp32 fallback (family / non-'a' passes): same signature/geometry,
// tile = 128 x 256 handled as two 128x128 halves. Uses x/y directly.
// ============================================================================
__global__ void __launch_bounds__(128, 2)
rbf_gemm_kernel(const __grid_constant__ CUtensorMap tmA,
                const __grid_constant__ CUtensorMap tmB,
                const float* __restrict__ x, const float* __restrict__ y,
                float* __restrict__ out) {
    extern __shared__ __align__(1024) char smem[];
    float* As = reinterpret_cast<float*>(smem);            // [16][128]
    float* Bs = As + 16 * 128;                             // [16][128]

    const int tid = threadIdx.x;
    const int tx = tid & 15;
    const int ty = tid >> 4;
    const int rowA = blockIdx.y * TM;

    for (int half = 0; half < 2; ++half) {
        const int rowB = blockIdx.x * TN + half * 128;

        float acc[16][8];
        #pragma unroll
        for (int i = 0; i < 16; ++i)
            #pragma unroll
            for (int j = 0; j < 8; ++j) acc[i][j] = 0.f;

        for (int k0 = 0; k0 < DDIM; k0 += 16) {
            #pragma unroll
            for (int it = 0; it < 16; ++it) {
                const int idx = it * 128 + tid;
                const int r  = idx >> 4;
                const int kk = idx & 15;
                As[kk * 128 + r] = x[(size_t)(rowA + r) * DDIM + k0 + kk];
                Bs[kk * 128 + r] = y[(size_t)(rowB + r) * DDIM + k0 + kk];
            }
            __syncthreads();
            #pragma unroll
            for (int kk = 0; kk < 16; ++kk) {
                float a[16], b[8];
                #pragma unroll
                for (int i = 0; i < 16; ++i) a[i] = As[kk * 128 + ty * 16 + i];
                #pragma unroll
                for (int j = 0; j < 8; ++j)  b[j] = Bs[kk * 128 + tx * 8 + j];
                #pragma unroll
                for (int i = 0; i < 16; ++i)
                    #pragma unroll
                    for (int j = 0; j < 8; ++j) acc[i][j] += a[i] * b[j];
            }
            __syncthreads();
        }

        #pragma unroll
        for (int i = 0; i < 16; ++i) {
            const int m = rowA + ty * 16 + i;
            const float xs = g_xsq[m];
            #pragma unroll
            for (int j = 0; j < 8; ++j) {
                const int cc = rowB + tx * 8 + j;
                float d = xs + g_ysq[cc] - 2.f * acc[i][j];
                out[(size_t)m * MROWS + cc] = __expf(-GAMMA * fmaxf(d, 0.f));
            }
        }
        __syncthreads();
    }
}
#endif // USE_TCGEN05

// ----------------------------------------------------------------------------
// Host: tensor-map construction via runtime driver-entry-point (no -lcuda).
// ----------------------------------------------------------------------------
typedef CUresult (*PFN_tmapEncode)(
    CUtensorMap*, CUtensorMapDataType, cuuint32_t, void*,
    const cuuint64_t*, const cuuint64_t*, const cuuint32_t*, const cuuint32_t*,
    CUtensorMapInterleave, CUtensorMapSwizzle, CUtensorMapL2promotion,
    CUtensorMapFloatOOBfill);

static PFN_tmapEncode get_tmap_encoder() {
    void* fn = nullptr;
    cudaDriverEntryPointQueryResult st;
#if CUDART_VERSION >= 12050
    cudaGetDriverEntryPointByVersion("cuTensorMapEncodeTiled", &fn, 12000,
                                     cudaEnableDefault, &st);
#else
    cudaGetDriverEntryPoint("cuTensorMapEncodeTiled", &fn, cudaEnableDefault, &st);
#endif
    return (PFN_tmapEncode)fn;
}

static void encode_map(PFN_tmapEncode enc, CUtensorMap* tm, void* base,
                       uint64_t rows, uint32_t box_rows) {
    cuuint64_t gdim[2] = {DDIM, rows};
    cuuint64_t gstr[1] = {DDIM * sizeof(__half)};
    cuuint32_t box[2]  = {CHUNK_K, box_rows};     // 32 fp16 = 64B rows (SW64)
    cuuint32_t estr[2] = {1, 1};
    enc(tm, CU_TENSOR_MAP_DATA_TYPE_FLOAT16, 2, base, gdim, gstr, box, estr,
        CU_TENSOR_MAP_INTERLEAVE_NONE, CU_TENSOR_MAP_SWIZZLE_64B,
        CU_TENSOR_MAP_L2_PROMOTION_L2_128B, CU_TENSOR_MAP_FLOAT_OOB_FILL_NONE);
}

extern "C" void kernel_launch(void* const* d_in, const int* in_sizes, int n_in,
                              void* d_out, int out_size) {
    const float* x = (const float*)d_in[0];
    const float* y = (const float*)d_in[1];
    float* out = (float*)d_out;

    prep_kernel<<<NROWS / 8 + MROWS / 8, 256>>>(x, y);

    void* xh_ptr = nullptr;
    void* yh_ptr = nullptr;
    cudaGetSymbolAddress(&xh_ptr, g_xh);
    cudaGetSymbolAddress(&yh_ptr, g_yh);

    CUtensorMap tmA, tmB;
    PFN_tmapEncode enc = get_tmap_encoder();
    encode_map(enc, &tmA, xh_ptr, NROWS, TM);     // box [32, 128]
    encode_map(enc, &tmB, yh_ptr, MROWS, TN);     // box [32, 256]

    cudaFuncSetAttribute(rbf_gemm_kernel, cudaFuncAttributeMaxDynamicSharedMemorySize,
                         SMEM_TOTAL);
    dim3 grid(MROWS / TN, NROWS / TM);            // (32, 64)
    rbf_gemm_kernel<<<grid, 128, SMEM_TOTAL>>>(tmA, tmB, x, y, out);
}

// round 11
// speedup vs baseline: 1.4102x; 1.0076x over previous
#include <cuda_runtime.h>
#include <cuda_fp16.h>
#include <cuda.h>
#include <cstdint>

// ----------------------------------------------------------------------------
// Problem constants
// ----------------------------------------------------------------------------
#define NROWS 8192   // x rows (output rows)
#define MROWS 8192   // y rows (output cols)
#define DDIM  512
#define GAMMA 0.002f

#define TM 128
#define TN 256
#define CHUNK_K 32                   // fp16 elems per K-chunk (64B rows, SW64)
#define NCHUNKS (DDIM / CHUNK_K)     // 16
#define NSTAGES 4

// tcgen05 is arch-specific (sm_103a); the family (plain sm_103) pass needs a fallback.
#if !defined(__CUDA_ARCH__)
#  define USE_TCGEN05 1
#elif defined(__CUDA_ARCH_FEAT_SM103_ALL) || defined(__CUDA_ARCH_FEAT_SM100_ALL)
#  define USE_TCGEN05 1
#elif defined(__CUDA_ARCH_SPECIFIC__)
#  define USE_TCGEN05 1
#else
#  define USE_TCGEN05 0
#endif

// ----------------------------------------------------------------------------
// Scratch (device globals — no allocation allowed)
// ----------------------------------------------------------------------------
__device__ __half g_xh[NROWS * DDIM];
__device__ __half g_yh[MROWS * DDIM];
__device__ float  g_xsq[NROWS];
__device__ float  g_ysq[MROWS];

// ----------------------------------------------------------------------------
// Prep: fp32 -> fp16 + row |v|^2 (fp32 exact). One launch covers x then y.
// ----------------------------------------------------------------------------
__global__ void __launch_bounds__(256) prep_kernel(const float* __restrict__ x,
                                                   const float* __restrict__ y) {
    const int xblocks = NROWS / 8;
    const int which = (blockIdx.x >= xblocks) ? 1 : 0;
    const int blk   = which ? (blockIdx.x - xblocks) : blockIdx.x;
    const float* in = which ? y : x;
    __half* h  = which ? g_yh : g_xh;
    float* sq  = which ? g_ysq : g_xsq;

    const int warp = threadIdx.x >> 5;
    const int lane = threadIdx.x & 31;
    const int row  = blk * 8 + warp;
    const float* src = in + (size_t)row * DDIM;

    float s = 0.f;
    #pragma unroll
    for (int it = 0; it < 4; ++it) {
        const int col = it * 128 + lane * 4;
        const float4 v = *reinterpret_cast<const float4*>(src + col);
        s += v.x * v.x + v.y * v.y + v.z * v.z + v.w * v.w;
        __half2 p0 = __floats2half2_rn(v.x, v.y);
        __half2 p1 = __floats2half2_rn(v.z, v.w);
        uint2 hv = make_uint2(*reinterpret_cast<uint32_t*>(&p0),
                              *reinterpret_cast<uint32_t*>(&p1));
        *reinterpret_cast<uint2*>(h + (size_t)row * DDIM + col) = hv;
    }
    #pragma unroll
    for (int o = 16; o; o >>= 1) s += __shfl_xor_sync(0xffffffff, s, o);
    if (lane == 0) sq[row] = s;
}

// ----------------------------------------------------------------------------
// SMEM layout:
//   header 1024B: [0] tmem ptr, full[s] at 8+8s (s=0..3), done[s] at 40+8s
//   4 stages x (A 8K | B 16K) = 96K     -> total 99328 (2 CTAs/SM)
// ----------------------------------------------------------------------------
#define A_TILE_BYTES  (TM * CHUNK_K * 2)      // 8192  (64B rows)
#define B_TILE_BYTES  (TN * CHUNK_K * 2)      // 16384
#define STAGE_BYTES   (A_TILE_BYTES + B_TILE_BYTES)          // 24576
#define SMEM_FULL(s)  (8 + 8 * (s))
#define SMEM_DONE(s)  (40 + 8 * (s))
#define SMEM_TILES    1024
#define SMEM_TOTAL    (SMEM_TILES + NSTAGES * STAGE_BYTES)   // 99328

#if USE_TCGEN05
// ============================================================================
// tcgen05 + TMA (SW64, 4-stage, deferred refill) — sm_103a passes only
// ============================================================================
__device__ __forceinline__ uint32_t smem_u32(const void* p) {
    uint32_t a;
    asm("{ .reg .u64 t; cvta.to.shared.u64 t, %1; cvt.u32.u64 %0, t; }" : "=r"(a) : "l"(p));
    return a;
}

#define TCGEN05_ALLOC(smem_addr, ncols) \
    asm volatile("tcgen05.alloc.cta_group::1.sync.aligned.shared::cta.b32 [%0], %1;" \
                 :: "r"((uint32_t)(smem_addr)), "r"((uint32_t)(ncols)) : "memory")
#define TCGEN05_DEALLOC(tmem, ncols) \
    asm volatile("tcgen05.dealloc.cta_group::1.sync.aligned.b32 %0, %1;" \
                 :: "r"(tmem), "r"((uint32_t)(ncols)))
#define TCGEN05_RELINQ() \
    asm volatile("tcgen05.relinquish_alloc_permit.cta_group::1.sync.aligned;")
#define TCGEN05_COMMIT(mbar) \
    asm volatile("tcgen05.commit.cta_group::1.mbarrier::arrive::one.shared::cluster.b64 [%0];" \
                 :: "r"((uint32_t)(mbar)) : "memory")
#define TCGEN05_WAIT_LD() asm volatile("tcgen05.wait::ld.sync.aligned;" ::: "memory")
#define TCGEN05_FENCE_AFTER()  asm volatile("tcgen05.fence::after_thread_sync;" ::: "memory")
#define TCGEN05_FENCE_BEFORE() asm volatile("tcgen05.fence::before_thread_sync;" ::: "memory")

#define MBARRIER_INIT(mbar, cnt) \
    asm volatile("mbarrier.init.shared.b64 [%0], %1;" \
                 :: "r"((uint32_t)(mbar)), "r"((uint32_t)(cnt)) : "memory")
#define MBARRIER_INVAL(mbar) \
    asm volatile("mbarrier.inval.shared.b64 [%0];" :: "r"((uint32_t)(mbar)) : "memory")
#define MBARRIER_EXPECT_TX(mbar, bytes) \
    asm volatile("mbarrier.arrive.expect_tx.shared.b64 _, [%0], %1;" \
                 :: "r"((uint32_t)(mbar)), "r"((uint32_t)(bytes)) : "memory")

#define MBARRIER_WAIT_PARITY(mbar, parity) do {                                         \
    uint32_t _m = (uint32_t)(mbar);                                                     \
    uint32_t _p = (uint32_t)(parity);                                                   \
    uint32_t _done;                                                                     \
    asm volatile("{\n\t.reg .pred p;\n\t"                                               \
                 "mbarrier.try_wait.parity.acquire.cta.shared::cta.b64 p, [%1], %2;\n\t"\
                 "selp.b32 %0, 1, 0, p;\n\t}"                                           \
                 : "=r"(_done) : "r"(_m), "r"(_p) : "memory");                          \
    if (!_done) {                                                                       \
        asm volatile("{\n\t.reg .pred P1;\n\t"                                          \
            "WAIT_LOOP_%=:\n\t"                                                         \
            "mbarrier.try_wait.parity.acquire.cta.shared::cta.b64 P1, [%0], %1, 0x989680;\n\t" \
            "@P1 bra.uni WAIT_DONE_%=;\n\t"                                             \
            "bra.uni WAIT_LOOP_%=;\n\t"                                                 \
            "WAIT_DONE_%=:\n\t}"                                                        \
            :: "r"(_m), "r"(_p) : "memory");                                            \
    }                                                                                   \
} while (0)

#define TCGEN05_LD_32X32B_X32(r, tmem_addr) \
    asm volatile( \
        "tcgen05.ld.sync.aligned.32x32b.x32.b32 " \
        "{%0, %1, %2, %3, %4, %5, %6, %7, " \
        " %8, %9, %10, %11, %12, %13, %14, %15, " \
        " %16, %17, %18, %19, %20, %21, %22, %23, " \
        " %24, %25, %26, %27, %28, %29, %30, %31}, [%32];" \
        : "=r"((r)[0]),  "=r"((r)[1]),  "=r"((r)[2]),  "=r"((r)[3]), \
          "=r"((r)[4]),  "=r"((r)[5]),  "=r"((r)[6]),  "=r"((r)[7]), \
          "=r"((r)[8]),  "=r"((r)[9]),  "=r"((r)[10]), "=r"((r)[11]), \
          "=r"((r)[12]), "=r"((r)[13]), "=r"((r)[14]), "=r"((r)[15]), \
          "=r"((r)[16]), "=r"((r)[17]), "=r"((r)[18]), "=r"((r)[19]), \
          "=r"((r)[20]), "=r"((r)[21]), "=r"((r)[22]), "=r"((r)[23]), \
          "=r"((r)[24]), "=r"((r)[25]), "=r"((r)[26]), "=r"((r)[27]), \
          "=r"((r)[28]), "=r"((r)[29]), "=r"((r)[30]), "=r"((r)[31]) \
        : "r"(tmem_addr))

__device__ __forceinline__ void tma_load_2d(uint32_t sdst, const CUtensorMap* tm,
                                            int c0, int c1, uint32_t mbar) {
    asm volatile(
        "cp.async.bulk.tensor.2d.shared::cta.global.tile.mbarrier::complete_tx::bytes "
        "[%0], [%1, {%2, %3}], [%4];"
        :: "r"(sdst), "l"(tm), "r"(c0), "r"(c1), "r"(mbar) : "memory");
}

__device__ __forceinline__ void mma_f16_ss(uint32_t d_tmem, uint64_t a_desc,
                                           uint64_t b_desc, uint32_t idesc,
                                           uint32_t enable) {
    asm volatile(
        "{\n\t.reg .pred p;\n\tsetp.ne.u32 p, %4, 0;\n\t"
        "tcgen05.mma.cta_group::1.kind::f16 [%0], %1, %2, %3, {%5, %5, %5, %5}, p;\n\t}"
        :: "r"(d_tmem), "l"(a_desc), "l"(b_desc), "r"(idesc), "r"(enable), "r"(0u)
        : "memory");
}

// SW64 SMEM descriptor: layout=4, version=1(Blackwell), SBO=32 (8 rows x 64B =
// 512B), LBO=1 (16B inner). 64-byte K-major rows.
static __device__ __forceinline__ uint64_t make_desc_sw64(uint32_t smem_addr) {
    constexpr uint64_t BASE =
        (uint64_t(4) << 61) | (uint64_t(1) << 46) | (uint64_t(32) << 32) | (uint64_t(1) << 16);
    return BASE | ((uint64_t)(smem_addr >> 4) & 0x3FFF);
}

// idesc for kind::f16, fp16 inputs, fp32 accum (bit4), N=256, M=128
#define MMA_IDESC ((1u << 4) | (((unsigned)TN / 8) << 17) | (((unsigned)TM / 16) << 24))

__global__ void __launch_bounds__(128, 2)
rbf_gemm_kernel(const __grid_constant__ CUtensorMap tmA,
                const __grid_constant__ CUtensorMap tmB,
                const float* __restrict__ x, const float* __restrict__ y,
                float* __restrict__ out) {
    extern __shared__ __align__(1024) char smem[];
    const uint32_t sb  = smem_u32(smem);
    const int tid = threadIdx.x;
    const int wid = tid >> 5;
    const int lid = tid & 31;

    if (wid == 0) {
        TCGEN05_ALLOC(sb, 256);
        TCGEN05_RELINQ();
    }
    __syncthreads();
    uint32_t tmem;
    asm volatile("ld.shared.b32 %0, [%1];" : "=r"(tmem) : "r"(sb));

    if (tid == 0) {
        #pragma unroll
        for (int s = 0; s < NSTAGES; ++s) {
            MBARRIER_INIT(sb + SMEM_FULL(s), 1);
            MBARRIER_INIT(sb + SMEM_DONE(s), 1);
        }
    }
    __syncthreads();

    const int rowA = blockIdx.y * TM;
    const int rowB = blockIdx.x * TN;

    // ------------------------------------------------------------------
    // Mainloop with DEFERRED refill: at iteration c we load chunk c+3 into
    // stage (c+3)&3 = (c-1)&3 — whose last MMA (chunk c-1) was committed a
    // full iteration ago, so the done-wait is (near-)instant and the TMA
    // issue is no longer serialized behind a just-issued MMA. Up to 3
    // stages (72KB) of TMA stay in flight per CTA.
    // ------------------------------------------------------------------
    if (tid == 0) {
        // Prologue: chunks 0..2 into stages 0..2 (stage 3 filled at iter 0).
        #pragma unroll
        for (int s = 0; s < 3; ++s) {
            const uint32_t st = sb + SMEM_TILES + s * STAGE_BYTES;
            MBARRIER_EXPECT_TX(sb + SMEM_FULL(s), STAGE_BYTES);
            tma_load_2d(st + A_TILE_BYTES, &tmB, s * CHUNK_K, rowB, sb + SMEM_FULL(s));
            tma_load_2d(st, &tmA, s * CHUNK_K, rowA, sb + SMEM_FULL(s));
        }

        #pragma unroll
        for (int c = 0; c < NCHUNKS; ++c) {
            const int s = c & (NSTAGES - 1);
            const uint32_t st = sb + SMEM_TILES + s * STAGE_BYTES;

            MBARRIER_WAIT_PARITY(sb + SMEM_FULL(s), (c >> 2) & 1);

            const uint64_t dA = make_desc_sw64(st);
            const uint64_t dB = make_desc_sw64(st + A_TILE_BYTES);
            // 2 x K=16 MMAs; +32B (=2 desc units) per step within the 64B row.
            mma_f16_ss(tmem, dA,     dB,     MMA_IDESC, (c == 0) ? 0u : 1u);
            mma_f16_ss(tmem, dA + 2, dB + 2, MMA_IDESC, 1u);
            TCGEN05_COMMIT(sb + SMEM_DONE(s));

            // Deferred refill: chunk g = c+3 into stage g&3 == (c-1)&3.
            const int g = c + 3;
            if (g < NCHUNKS) {
                const int s2 = g & (NSTAGES - 1);
                const uint32_t st2 = sb + SMEM_TILES + s2 * STAGE_BYTES;
                if (c >= 1)   // stage s2's previous user was chunk c-1
                    MBARRIER_WAIT_PARITY(sb + SMEM_DONE(s2), ((c - 1) >> 2) & 1);
                MBARRIER_EXPECT_TX(sb + SMEM_FULL(s2), STAGE_BYTES);
                tma_load_2d(st2 + A_TILE_BYTES, &tmB, g * CHUNK_K, rowB,
                            sb + SMEM_FULL(s2));
                tma_load_2d(st2, &tmA, g * CHUNK_K, rowA, sb + SMEM_FULL(s2));
            }
        }
        // Stage 3 commits at c=3,7,11,15 (parities 0,1,0,1); refills consumed
        // parities 0,1,0 (at c=4,8,12) -> final wait parity 1 covers chunk 15,
        // and commit ordering implies all earlier MMAs are complete too.
        MBARRIER_WAIT_PARITY(sb + SMEM_DONE(3), 1);
    }

    __syncthreads();
    TCGEN05_FENCE_AFTER();

    // ------------------------------------------------------------------
    // Epilogue: each warp owns its 32-row TMEM subpartition; TN=256 cols.
    // __stwt keeps the fp16 operand set L2-resident.
    // ------------------------------------------------------------------
    const int m = rowA + wid * 32 + lid;
    const float xs = g_xsq[m];
    float* orow = out + (size_t)m * MROWS + rowB;

    #pragma unroll
    for (int nb = 0; nb < TN / 32; ++nb) {
        uint32_t r[32];
        TCGEN05_LD_32X32B_X32(r, tmem + nb * 32);
        TCGEN05_WAIT_LD();
        #pragma unroll
        for (int j = 0; j < 32; j += 4) {
            float4 o;
            float d0 = xs + g_ysq[rowB + nb * 32 + j + 0] - 2.f * __uint_as_float(r[j + 0]);
            float d1 = xs + g_ysq[rowB + nb * 32 + j + 1] - 2.f * __uint_as_float(r[j + 1]);
            float d2 = xs + g_ysq[rowB + nb * 32 + j + 2] - 2.f * __uint_as_float(r[j + 2]);
            float d3 = xs + g_ysq[rowB + nb * 32 + j + 3] - 2.f * __uint_as_float(r[j + 3]);
            o.x = __expf(-GAMMA * fmaxf(d0, 0.f));
            o.y = __expf(-GAMMA * fmaxf(d1, 0.f));
            o.z = __expf(-GAMMA * fmaxf(d2, 0.f));
            o.w = __expf(-GAMMA * fmaxf(d3, 0.f));
            __stwt(reinterpret_cast<float4*>(orow + nb * 32 + j), o);
        }
    }
    TCGEN05_FENCE_BEFORE();

    __syncthreads();
    if (tid == 0) {
        #pragma unroll
        for (int s = 0; s < NSTAGES; ++s) {
            MBARRIER_INVAL(sb + SMEM_FULL(s));
            MBARRIER_INVAL(sb + SMEM_DONE(s));
        }
    }
    __syncthreads();
    if (wid == 0) TCGEN05_DEALLOC(tmem, 256);
}

#else  // !USE_TCGEN05
// ============================================================================
// SIMT fp32 fallback (family / non-'a' passes): same signature/geometry,
// tile = 128 x 256 handled as two 128x128 halves. Uses x/y directly.
// ============================================================================
__global__ void __launch_bounds__(128, 2)
rbf_gemm_kernel(const __grid_constant__ CUtensorMap tmA,
                const __grid_constant__ CUtensorMap tmB,
                const float* __restrict__ x, const float* __restrict__ y,
                float* __restrict__ out) {
    extern __shared__ __align__(1024) char smem[];
    float* As = reinterpret_cast<float*>(smem);            // [16][128]
    float* Bs = As + 16 * 128;                             // [16][128]

    const int tid = threadIdx.x;
    const int tx = tid & 15;
    const int ty = tid >> 4;
    const int rowA = blockIdx.y * TM;

    for (int half = 0; half < 2; ++half) {
        const int rowB = blockIdx.x * TN + half * 128;

        float acc[16][8];
        #pragma unroll
        for (int i = 0; i < 16; ++i)
            #pragma unroll
            for (int j = 0; j < 8; ++j) acc[i][j] = 0.f;

        for (int k0 = 0; k0 < DDIM; k0 += 16) {
            #pragma unroll
            for (int it = 0; it < 16; ++it) {
                const int idx = it * 128 + tid;
                const int r  = idx >> 4;
                const int kk = idx & 15;
                As[kk * 128 + r] = x[(size_t)(rowA + r) * DDIM + k0 + kk];
                Bs[kk * 128 + r] = y[(size_t)(rowB + r) * DDIM + k0 + kk];
            }
            __syncthreads();
            #pragma unroll
            for (int kk = 0; kk < 16; ++kk) {
                float a[16], b[8];
                #pragma unroll
                for (int i = 0; i < 16; ++i) a[i] = As[kk * 128 + ty * 16 + i];
                #pragma unroll
                for (int j = 0; j < 8; ++j)  b[j] = Bs[kk * 128 + tx * 8 + j];
                #pragma unroll
                for (int i = 0; i < 16; ++i)
                    #pragma unroll
                    for (int j = 0; j < 8; ++j) acc[i][j] += a[i] * b[j];
            }
            __syncthreads();
        }

        #pragma unroll
        for (int i = 0; i < 16; ++i) {
            const int m = rowA + ty * 16 + i;
            const float xs = g_xsq[m];
            #pragma unroll
            for (int j = 0; j < 8; ++j) {
                const int cc = rowB + tx * 8 + j;
                float d = xs + g_ysq[cc] - 2.f * acc[i][j];
                out[(size_t)m * MROWS + cc] = __expf(-GAMMA * fmaxf(d, 0.f));
            }
        }
        __syncthreads();
    }
}
#endif // USE_TCGEN05

// ----------------------------------------------------------------------------
// Host: tensor-map construction via runtime driver-entry-point (no -lcuda).
// ----------------------------------------------------------------------------
typedef CUresult (*PFN_tmapEncode)(
    CUtensorMap*, CUtensorMapDataType, cuuint32_t, void*,
    const cuuint64_t*, const cuuint64_t*, const cuuint32_t*, const cuuint32_t*,
    CUtensorMapInterleave, CUtensorMapSwizzle, CUtensorMapL2promotion,
    CUtensorMapFloatOOBfill);

static PFN_tmapEncode get_tmap_encoder() {
    void* fn = nullptr;
    cudaDriverEntryPointQueryResult st;
#if CUDART_VERSION >= 12050
    cudaGetDriverEntryPointByVersion("cuTensorMapEncodeTiled", &fn, 12000,
                                     cudaEnableDefault, &st);
#else
    cudaGetDriverEntryPoint("cuTensorMapEncodeTiled", &fn, cudaEnableDefault, &st);
#endif
    return (PFN_tmapEncode)fn;
}

static void encode_map(PFN_tmapEncode enc, CUtensorMap* tm, void* base,
                       uint64_t rows, uint32_t box_rows) {
    cuuint64_t gdim[2] = {DDIM, rows};
    cuuint64_t gstr[1] = {DDIM * sizeof(__half)};
    cuuint32_t box[2]  = {CHUNK_K, box_rows};     // 32 fp16 = 64B rows (SW64)
    cuuint32_t estr[2] = {1, 1};
    enc(tm, CU_TENSOR_MAP_DATA_TYPE_FLOAT16, 2, base, gdim, gstr, box, estr,
        CU_TENSOR_MAP_INTERLEAVE_NONE, CU_TENSOR_MAP_SWIZZLE_64B,
        CU_TENSOR_MAP_L2_PROMOTION_L2_128B, CU_TENSOR_MAP_FLOAT_OOB_FILL_NONE);
}

extern "C" void kernel_launch(void* const* d_in, const int* in_sizes, int n_in,
                              void* d_out, int out_size) {
    const float* x = (const float*)d_in[0];
    const float* y = (const float*)d_in[1];
    float* out = (float*)d_out;

    prep_kernel<<<NROWS / 8 + MROWS / 8, 256>>>(x, y);

    void* xh_ptr = nullptr;
    void* yh_ptr = nullptr;
    cudaGetSymbolAddress(&xh_ptr, g_xh);
    cudaGetSymbolAddress(&yh_ptr, g_yh);

    CUtensorMap tmA, tmB;
    PFN_tmapEncode enc = get_tmap_encoder();
    encode_map(enc, &tmA, xh_ptr, NROWS, TM);     // box [32, 128]
    encode_map(enc, &tmB, yh_ptr, MROWS, TN);     // box [32, 256]

    cudaFuncSetAttribute(rbf_gemm_kernel, cudaFuncAttributeMaxDynamicSharedMemorySize,
                         SMEM_TOTAL);
    dim3 grid(MROWS / TN, NROWS / TM);            // (32, 64)
    rbf_gemm_kernel<<<grid, 128, SMEM_TOTAL>>>(tmA, tmB, x, y, out);
}